// round 3
// baseline (speedup 1.0000x reference)
#include <cuda_runtime.h>
#include <math.h>

#define H 96
#define W 96
#define HW 9216
#define NB 2
#define CIN 256
#define CH 64

typedef unsigned long long ull;
union F2U { ull u; float2 f; };

__device__ __forceinline__ ull bcast2(float a) {
    ull r; asm("mov.b64 %0,{%1,%1};" : "=l"(r) : "f"(a)); return r;
}
__device__ __forceinline__ void ffma2(ull& d, ull a, ull b) {
    asm("fma.rn.f32x2 %0,%1,%2,%0;" : "+l"(d) : "l"(a), "l"(b));
}

// ---------------- scratch (device globals; no allocation allowed) ----------
__device__ float g_xh[NB*CH*HW];
__device__ float g_om[NB*27*HW];
__device__ float g_z [NB*CH*HW];
__device__ float g_r [NB*CH*HW];
__device__ float g_xe[NB*CH*HW];

// ---------------------------------------------------------------------------
// conv3x3, SAME, NCHW, input = concat(src0[C0], src1[Cin-C0]).
// Block 256 threads: OCT out-channels x 8x8 px tile; thread = 4oc x P px.
// Inner GEMM uses packed f32x2 FMA: weights are natural pairs from float4,
// inputs broadcast-packed once per tap column.
// ---------------------------------------------------------------------------
template<int OCT>
__global__ __launch_bounds__(256)
void conv3x3_kernel(const float* __restrict__ src0,
                    const float* __restrict__ src1,
                    int C0, int Cin,
                    const float* __restrict__ wgt,   // (Cout,Cin,3,3)
                    const float* __restrict__ bias,  // (Cout)
                    float* __restrict__ out, int Cout)
{
    constexpr int P  = OCT / 16;   // px per thread (4 or 2)
    constexpr int PG = 64 / P;     // px groups
    __shared__ float sIn[400];                       // 4ch x 10x10
    __shared__ __align__(16) float sW[4*9*OCT];

    const int tile = blockIdx.x;
    const int ty0  = (tile / 12) * 8;
    const int tx0  = (tile % 12) * 8;
    const int n    = blockIdx.z;
    const int ocBase = blockIdx.y * OCT;
    const int tid  = threadIdx.x;
    const int ocg  = tid / PG;          // 0..OCT/4-1
    const int pxg  = tid % PG;
    const int p0   = pxg * P;
    const int prow = p0 >> 3;
    const int pcol = p0 & 7;
    const int C1   = Cin - C0;

    ull accP[2][P];   // oc pairs (2a,2a+1) x px j
#pragma unroll
    for (int a = 0; a < 2; a++)
#pragma unroll
        for (int j = 0; j < P; j++) accP[a][j] = 0ull;

    for (int c0 = 0; c0 < Cin; c0 += 4) {
        // stage input patch: 4 channels x 10x10 (zero-padded SAME)
        for (int idx = tid; idx < 400; idx += 256) {
            int cc  = idx / 100;
            int rem = idx % 100;
            int r = rem / 10, cl = rem % 10;
            int gy = ty0 + r - 1, gx = tx0 + cl - 1;
            float v = 0.f;
            if ((unsigned)gy < H && (unsigned)gx < W) {
                int ch = c0 + cc;
                const float* sp = (ch < C0) ? (src0 + ((size_t)n*C0 + ch)*HW)
                                            : (src1 + ((size_t)n*C1 + (ch - C0))*HW);
                v = sp[gy*W + gx];
            }
            sIn[idx] = v;
        }
        // stage weights: sW[(cc*9+kk)*OCT + oc]
        for (int idx = tid; idx < 4*9*OCT; idx += 256) {
            int cc = idx / (9*OCT);
            int kk = (idx / OCT) % 9;
            int oc = idx % OCT;
            int go = ocBase + oc;
            sW[idx] = (go < Cout) ? wgt[((size_t)go*Cin + (c0+cc))*9 + kk] : 0.f;
        }
        __syncthreads();
#pragma unroll
        for (int cc = 0; cc < 4; cc++) {
#pragma unroll
            for (int ky = 0; ky < 3; ky++) {
                const float* irow = &sIn[cc*100 + (prow+ky)*10 + pcol];
                ull ip[P+2];
#pragma unroll
                for (int t = 0; t < P+2; t++) ip[t] = bcast2(irow[t]);
#pragma unroll
                for (int kx = 0; kx < 3; kx++) {
                    const ull* w2 = reinterpret_cast<const ull*>(
                        &sW[(cc*9 + ky*3 + kx)*OCT + (ocg<<2)]);
                    ull w20 = w2[0], w21 = w2[1];
#pragma unroll
                    for (int j = 0; j < P; j++) {
                        ffma2(accP[0][j], w20, ip[kx+j]);
                        ffma2(accP[1][j], w21, ip[kx+j]);
                    }
                }
            }
        }
        __syncthreads();
    }
#pragma unroll
    for (int a = 0; a < 2; a++) {
        int oc0 = ocBase + (ocg<<2) + 2*a;
        float b0 = (oc0     < Cout) ? bias[oc0]   : 0.f;
        float b1 = (oc0 + 1 < Cout) ? bias[oc0+1] : 0.f;
#pragma unroll
        for (int j = 0; j < P; j++) {
            F2U u; u.u = accP[a][j];
            size_t pix = (size_t)(ty0+prow)*W + tx0 + pcol + j;
            if (oc0 < Cout)
                out[((size_t)n*Cout + oc0)*HW + pix] = u.f.x + b0;
            if (oc0 + 1 < Cout)
                out[((size_t)n*Cout + oc0 + 1)*HW + pix] = u.f.y + b1;
        }
    }
}

// ---------------------------------------------------------------------------
// DCN main: bilinear-gather from concat(src0,src1)[128ch] with offsets om,
// GEMM with w(64,128,9), bias, activation.
// act=0: out = sigmoid(v)
// act=1: out = (1-z)*t + z*tanh(v)   (fused GRU combine)
// Weights staged in smem PRE-DUPLICATED as (w,w) f32x2 pairs -> inner loop is
// 3x LDS.128 + 8 FFMA2 per k-step, no packing MOVs.
// ---------------------------------------------------------------------------
#define DCN_SMEM 73728
extern __shared__ float dynsmem[];

__global__ __launch_bounds__(256)
void dcn_kernel(const float* __restrict__ src0,
                const float* __restrict__ src1,
                const float* __restrict__ om,
                const float* __restrict__ wgt,
                const float* __restrict__ bias,
                float* __restrict__ out, int act,
                const float* __restrict__ zbuf,
                const float* __restrict__ tbuf)
{
    ull*   sWtU = reinterpret_cast<ull*>(dynsmem);   // 4608 ull (36KB) dup weights
    float* sWgt = dynsmem + 9216;                    // 2304 f
    int*   sOff = (int*)(dynsmem + 11520);           // 2304 i
    float* sS   = dynsmem + 13824;                   // 4608 f (72 x 64)

    const int tile = blockIdx.x;
    const int n    = blockIdx.z;
    const int ty0  = (tile / 12) * 8;
    const int tx0  = (tile % 12) * 8;
    const int tid  = threadIdx.x;

    // ---- precompute per-(k,px) clamped corner offsets + (bilinear*mask) wgts
    for (int idx = tid; idx < 576; idx += 256) {
        int k = idx >> 6, p = idx & 63;
        int py = ty0 + (p >> 3), px = tx0 + (p & 7);
        int pix = py*W + px;
        float dy = om[((size_t)n*27 + k     )*HW + pix];
        float dx = om[((size_t)n*27 + 9  + k)*HW + pix];
        float mv = om[((size_t)n*27 + 18 + k)*HW + pix];
        float m  = 1.f / (1.f + __expf(-mv));
        float fy = (float)(py + (k/3) - 1) + dy;
        float fx = (float)(px + (k%3) - 1) + dx;
        float y0f = floorf(fy), x0f = floorf(fx);
        float wy = fy - y0f, wx = fx - x0f;
        y0f = fmaxf(fminf(y0f, 1.0e4f), -1.0e4f);
        x0f = fmaxf(fminf(x0f, 1.0e4f), -1.0e4f);
        int iy0 = (int)y0f, ix0 = (int)x0f;
        int iy1 = iy0 + 1,  ix1 = ix0 + 1;
        bool vy0 = (unsigned)iy0 < H, vy1 = (unsigned)iy1 < H;
        bool vx0 = (unsigned)ix0 < W, vx1 = (unsigned)ix1 < W;
        int cy0 = min(max(iy0,0),H-1), cy1 = min(max(iy1,0),H-1);
        int cx0 = min(max(ix0,0),W-1), cx1 = min(max(ix1,0),W-1);
        int b = idx << 2;
        sOff[b+0] = cy0*W + cx0;  sWgt[b+0] = (vy0 && vx0) ? (1.f-wy)*(1.f-wx)*m : 0.f;
        sOff[b+1] = cy0*W + cx1;  sWgt[b+1] = (vy0 && vx1) ? (1.f-wy)*wx*m       : 0.f;
        sOff[b+2] = cy1*W + cx0;  sWgt[b+2] = (vy1 && vx0) ? wy*(1.f-wx)*m       : 0.f;
        sOff[b+3] = cy1*W + cx1;  sWgt[b+3] = (vy1 && vx1) ? wy*wx*m             : 0.f;
    }
    __syncthreads();

    const int ocg = tid >> 4;   // 0..15 (4 oc each)
    const int pxg = tid & 15;   // 0..15 (4 px each)
    ull accP[4][2];             // oc i x px-pair pp
#pragma unroll
    for (int i = 0; i < 4; i++)
#pragma unroll
        for (int pp = 0; pp < 2; pp++) accP[i][pp] = 0ull;

    for (int ch0 = 0; ch0 < 128; ch0 += 8) {
        // stage gathered samples: sS[(cl*9+k)*64 + p]
        for (int idx = tid; idx < 4608; idx += 256) {
            int cl = idx / 576;
            int kp = idx % 576;
            int c  = ch0 + cl;
            const float* sp = (c < 64) ? (src0 + ((size_t)n*64 + c   )*HW)
                                       : (src1 + ((size_t)n*64 + c-64)*HW);
            int b = kp << 2;
            float v = sWgt[b+0] * __ldg(sp + sOff[b+0])
                    + sWgt[b+1] * __ldg(sp + sOff[b+1])
                    + sWgt[b+2] * __ldg(sp + sOff[b+2])
                    + sWgt[b+3] * __ldg(sp + sOff[b+3]);
            sS[idx] = v;
        }
        // stage weights duplicated: sWtU[kk*64 + oc] = (w,w)
        for (int idx = tid; idx < 4608; idx += 256) {
            int kk = idx >> 6;
            int oc = idx & 63;
            int cl = kk / 9, k = kk % 9;
            float w = wgt[((size_t)oc*128 + ch0 + cl)*9 + k];
            sWtU[idx] = bcast2(w);
        }
        __syncthreads();
#pragma unroll 4
        for (int kk = 0; kk < 72; kk++) {
            const ull* w2 = &sWtU[kk*64 + (ocg<<2)];             // 4 dup pairs
            const ull* s2 = reinterpret_cast<const ull*>(&sS[kk*64 + (pxg<<2)]);
            ull s20 = s2[0], s21 = s2[1];
            ull w20 = w2[0], w21 = w2[1], w22 = w2[2], w23 = w2[3];
            ffma2(accP[0][0], w20, s20); ffma2(accP[0][1], w20, s21);
            ffma2(accP[1][0], w21, s20); ffma2(accP[1][1], w21, s21);
            ffma2(accP[2][0], w22, s20); ffma2(accP[2][1], w22, s21);
            ffma2(accP[3][0], w23, s20); ffma2(accP[3][1], w23, s21);
        }
        __syncthreads();
    }

    const int p0 = pxg << 2;
    const int oy = ty0 + (p0 >> 3);
    const int ox = tx0 + (p0 & 7);
#pragma unroll
    for (int i = 0; i < 4; i++) {
        int oc = (ocg<<2) + i;
        float b = bias[oc];
        size_t base = ((size_t)n*64 + oc)*HW + (size_t)oy*W + ox;
#pragma unroll
        for (int pp = 0; pp < 2; pp++) {
            F2U u; u.u = accP[i][pp];
            float v0 = u.f.x + b, v1 = u.f.y + b;
            size_t i0 = base + 2*pp, i1 = base + 2*pp + 1;
            if (act == 0) {
                out[i0] = 1.f / (1.f + __expf(-v0));
                out[i1] = 1.f / (1.f + __expf(-v1));
            } else {
                float z0 = zbuf[i0], z1 = zbuf[i1];
                out[i0] = (1.f - z0) * tbuf[i0] + z0 * tanhf(v0);
                out[i1] = (1.f - z1) * tbuf[i1] + z1 * tanhf(v1);
            }
        }
    }
}

// ---------------------------------------------------------------------------
// NCF: 49-tap (r=3, dil=2) correlation softmax-attention sample.
// Block 256 threads = 64 pixels x 4 channel-groups (16 ch each).
// ---------------------------------------------------------------------------
__global__ void ncf_kernel(const float* __restrict__ f1,
                           const float* __restrict__ f2,
                           float* __restrict__ rout)
{
    const int tid = threadIdx.x;
    const int cg  = tid & 3;
    const int pl  = tid >> 2;
    const int gp  = blockIdx.x * 64 + pl;   // 0 .. N*HW-1
    const int n   = gp / HW;
    const int pix = gp % HW;
    const int y   = pix / W, x = pix % W;

    unsigned long long vmask = 0ull;
#pragma unroll
    for (int k = 0; k < 49; k++) {
        int yy = y + (k/7)*2 - 6;
        int xx = x + (k%7)*2 - 6;
        if ((unsigned)yy < H && (unsigned)xx < W) vmask |= (1ull << k);
    }

    float corr[49];
#pragma unroll
    for (int k = 0; k < 49; k++) corr[k] = 0.f;

    const float* f1b = f1 + (size_t)n*64*HW + pix;
    const float* f2b = f2 + (size_t)n*64*HW + pix;

#pragma unroll 1
    for (int ci = 0; ci < 16; ci++) {
        int c = cg*16 + ci;
        float a = f1b[(size_t)c*HW];
        const float* fp = f2b + (size_t)c*HW;
#pragma unroll
        for (int k = 0; k < 49; k++) {
            int off = ((k/7)*2 - 6)*W + (k%7)*2 - 6;
            float v = ((vmask >> k) & 1ull) ? __ldg(fp + off) : 0.f;
            corr[k] = fmaf(a, v, corr[k]);
        }
    }
#pragma unroll
    for (int k = 0; k < 49; k++) {
        corr[k] += __shfl_xor_sync(0xffffffffu, corr[k], 1);
        corr[k] += __shfl_xor_sync(0xffffffffu, corr[k], 2);
        corr[k] *= 0.125f;   // 1/sqrt(64)
    }
    float mx = corr[0];
#pragma unroll
    for (int k = 1; k < 49; k++) mx = fmaxf(mx, corr[k]);
    float s = 0.f;
#pragma unroll
    for (int k = 0; k < 49; k++) { corr[k] = __expf(corr[k] - mx); s += corr[k]; }
    float inv = 1.f / s;
#pragma unroll
    for (int k = 0; k < 49; k++) corr[k] *= inv;

#pragma unroll 1
    for (int ci = 0; ci < 16; ci++) {
        int c = cg*16 + ci;
        const float* fp = f2b + (size_t)c*HW;
        float av = 0.f;
#pragma unroll
        for (int k = 0; k < 49; k++) {
            int off = ((k/7)*2 - 6)*W + (k%7)*2 - 6;
            float v = ((vmask >> k) & 1ull) ? __ldg(fp + off) : 0.f;
            av = fmaf(corr[k], v, av);
        }
        rout[((size_t)n*64 + c)*HW + pix] = av;
    }
}

// ---------------------------------------------------------------------------
extern "C" void kernel_launch(void* const* d_in, const int* in_sizes, int n_in,
                              void* d_out, int out_size)
{
    const float* X    = (const float*)d_in[0];
    const float* T    = (const float*)d_in[1];
    const float* Wi   = (const float*)d_in[2];
    const float* Bi   = (const float*)d_in[3];
    const float* Wo   = (const float*)d_in[4];
    const float* Bo   = (const float*)d_in[5];
    const float* EZW  = (const float*)d_in[6];
    const float* EZB  = (const float*)d_in[7];
    const float* EZOW = (const float*)d_in[8];
    const float* EZOB = (const float*)d_in[9];
    const float* EHW  = (const float*)d_in[10];
    const float* EHB  = (const float*)d_in[11];
    const float* EHOW = (const float*)d_in[12];
    const float* EHOB = (const float*)d_in[13];
    const float* UZW  = (const float*)d_in[14];
    const float* UZB  = (const float*)d_in[15];
    const float* UZOW = (const float*)d_in[16];
    const float* UZOB = (const float*)d_in[17];
    const float* UHW  = (const float*)d_in[18];
    const float* UHB  = (const float*)d_in[19];
    const float* UHOW = (const float*)d_in[20];
    const float* UHOB = (const float*)d_in[21];

    float* out  = (float*)d_out;
    float* newt = out + (size_t)NB*CIN*HW;

    float *xh, *om, *zb, *rb, *xe;
    cudaGetSymbolAddress((void**)&xh, g_xh);
    cudaGetSymbolAddress((void**)&om, g_om);
    cudaGetSymbolAddress((void**)&zb, g_z);
    cudaGetSymbolAddress((void**)&rb, g_r);
    cudaGetSymbolAddress((void**)&xe, g_xe);

    cudaFuncSetAttribute(dcn_kernel,
                         cudaFuncAttributeMaxDynamicSharedMemorySize, DCN_SMEM);

    dim3 g144(144, 1, NB);

    // xh = conv_in(x)
    conv3x3_kernel<64><<<g144, 256>>>(X, X, CIN, CIN, Wi, Bi, xh, CH);

    // ---- enh branch: stargru(x=template, t=xh) ----
    conv3x3_kernel<32><<<g144, 256>>>(T, xh, CH, 2*CH, EZOW, EZOB, om, 27);
    dcn_kernel<<<g144, 256, DCN_SMEM>>>(T, xh, om, EZW, EZB, zb, 0, nullptr, nullptr);
    ncf_kernel<<<NB*HW/64, 256>>>(xh, T, rb);
    conv3x3_kernel<32><<<g144, 256>>>(rb, xh, CH, 2*CH, EHOW, EHOB, om, 27);
    dcn_kernel<<<g144, 256, DCN_SMEM>>>(rb, xh, om, EHW, EHB, xe, 1, zb, xh);

    // out = conv_out(x_enh)
    conv3x3_kernel<64><<<dim3(144, 4, NB), 256>>>(xe, xe, CH, CH, Wo, Bo, out, CIN);

    // ---- upd branch: stargru(x=xh, t=template) ----
    conv3x3_kernel<32><<<g144, 256>>>(xh, T, CH, 2*CH, UZOW, UZOB, om, 27);
    dcn_kernel<<<g144, 256, DCN_SMEM>>>(xh, T, om, UZW, UZB, zb, 0, nullptr, nullptr);
    ncf_kernel<<<NB*HW/64, 256>>>(T, xh, rb);
    conv3x3_kernel<32><<<g144, 256>>>(rb, T, CH, 2*CH, UHOW, UHOB, om, 27);
    dcn_kernel<<<g144, 256, DCN_SMEM>>>(rb, T, om, UHW, UHB, newt, 1, zb, T);
}

// round 6
// speedup vs baseline: 1.0388x; 1.0388x over previous
#include <cuda_runtime.h>
#include <math.h>

#define H 96
#define W 96
#define HW 9216
#define NB 2
#define CIN 256
#define CH 64

typedef unsigned long long ull;
union F2U { ull u; float2 f; };

__device__ __forceinline__ ull bcast2(float a) {
    ull r; asm("mov.b64 %0,{%1,%1};" : "=l"(r) : "f"(a)); return r;
}
__device__ __forceinline__ void ffma2(ull& d, ull a, ull b) {
    asm("fma.rn.f32x2 %0,%1,%2,%0;" : "+l"(d) : "l"(a), "l"(b));
}

// ---------------- scratch (device globals; no allocation allowed) ----------
__device__ float g_xh [NB*CH*HW];
__device__ float g_om0[NB*27*HW];
__device__ float g_om1[NB*27*HW];
__device__ float g_z0 [NB*CH*HW];
__device__ float g_z1 [NB*CH*HW];
__device__ float g_r0 [NB*CH*HW];
__device__ float g_r1 [NB*CH*HW];
__device__ float g_xe [NB*CH*HW];

// ---------------------------------------------------------------------------
// conv3x3, SAME, NCHW, input = concat(src0[C0], src1[Cin-C0]).
// OCT=32: block 256 threads = 32 oc x 8x8 px tile; thread = 4oc x 2px.
// Double-buffered smem staging: one __syncthreads per 4-channel k-step,
// next chunk's LDGs overlap current chunk's FFMA2s.
// grid: (144, Cout/32, NB*nBranch); branch = z/NB, n = z%NB.
// ---------------------------------------------------------------------------
struct ConvArgs {
    const float* src0[2];
    const float* src1[2];
    const float* wgt[2];   // (Cout,Cin,3,3)
    const float* bias[2];  // (Cout)
    float*       out[2];
};

__global__ __launch_bounds__(256)
void conv3x3_kernel(ConvArgs args, int C0, int Cin, int Cout)
{
    __shared__ float sIn[2][400];                      // 4ch x 10x10
    __shared__ __align__(16) float sW[2][1152];        // 4ch x 9 x 32oc

    const int tile = blockIdx.x;
    const int ty0  = (tile / 12) * 8;
    const int tx0  = (tile % 12) * 8;
    const int branch = blockIdx.z / NB;
    const int n      = blockIdx.z % NB;
    const int ocBase = blockIdx.y * 32;
    const int tid  = threadIdx.x;
    const int ocg  = tid >> 5;          // 0..7 (4 oc each) — uniform per warp
    const int pxg  = tid & 31;          // 0..31 (2 px each)
    const int p0   = pxg * 2;
    const int prow = p0 >> 3;
    const int pcol = p0 & 7;
    const int C1   = Cin - C0;

    const float* __restrict__ src0 = args.src0[branch];
    const float* __restrict__ src1 = args.src1[branch];
    const float* __restrict__ wgt  = args.wgt[branch];
    const float* __restrict__ bias = args.bias[branch];
    float*       __restrict__ out  = args.out[branch];

    ull acc[2][2];
#pragma unroll
    for (int a = 0; a < 2; a++)
#pragma unroll
        for (int j = 0; j < 2; j++) acc[a][j] = 0ull;

    float rIn[2], rW[5];

    auto loadChunk = [&](int c0) {
#pragma unroll
        for (int j = 0; j < 2; j++) {
            int idx = tid + j*256;
            float v = 0.f;
            if (idx < 400) {
                int cc  = idx / 100;
                int rem = idx % 100;
                int r = rem / 10, cl = rem % 10;
                int gy = ty0 + r - 1, gx = tx0 + cl - 1;
                if ((unsigned)gy < H && (unsigned)gx < W) {
                    int ch = c0 + cc;
                    const float* sp = (ch < C0)
                        ? (src0 + ((size_t)n*C0 + ch)*HW)
                        : (src1 + ((size_t)n*C1 + (ch - C0))*HW);
                    v = __ldg(sp + gy*W + gx);
                }
            }
            rIn[j] = v;
        }
#pragma unroll
        for (int j = 0; j < 5; j++) {
            int idx = tid + j*256;
            float v = 0.f;
            if (idx < 1152) {
                int cc = idx / 288;         // 288 = 9*32
                int kk = (idx >> 5) % 9;
                int oc = idx & 31;
                int go = ocBase + oc;
                if (go < Cout)
                    v = __ldg(&wgt[((size_t)go*Cin + (c0+cc))*9 + kk]);
            }
            rW[j] = v;
        }
    };
    auto storeChunk = [&](int buf) {
#pragma unroll
        for (int j = 0; j < 2; j++) {
            int idx = tid + j*256;
            if (idx < 400) sIn[buf][idx] = rIn[j];
        }
#pragma unroll
        for (int j = 0; j < 5; j++) {
            int idx = tid + j*256;
            if (idx < 1152) sW[buf][idx] = rW[j];
        }
    };

    loadChunk(0);
    storeChunk(0);
    __syncthreads();

    int cur = 0;
    for (int c0 = 0; c0 < Cin; c0 += 4) {
        bool more = (c0 + 4 < Cin);
        if (more) loadChunk(c0 + 4);          // LDGs overlap compute below
#pragma unroll
        for (int cc = 0; cc < 4; cc++) {
#pragma unroll
            for (int ky = 0; ky < 3; ky++) {
                const float* irow = &sIn[cur][cc*100 + (prow+ky)*10 + pcol];
                ull ip[4];
#pragma unroll
                for (int t = 0; t < 4; t++) ip[t] = bcast2(irow[t]);
#pragma unroll
                for (int kx = 0; kx < 3; kx++) {
                    const ull* w2 = reinterpret_cast<const ull*>(
                        &sW[cur][(cc*9 + ky*3 + kx)*32 + (ocg<<2)]);
                    ull w20 = w2[0], w21 = w2[1];
#pragma unroll
                    for (int j = 0; j < 2; j++) {
                        ffma2(acc[0][j], w20, ip[kx+j]);
                        ffma2(acc[1][j], w21, ip[kx+j]);
                    }
                }
            }
        }
        if (more) storeChunk(cur ^ 1);        // safe: buf^1 last read 2 steps ago
        __syncthreads();
        cur ^= 1;
    }

#pragma unroll
    for (int a = 0; a < 2; a++) {
        int oc0 = ocBase + (ocg<<2) + 2*a;
        float b0 = (oc0     < Cout) ? bias[oc0]   : 0.f;
        float b1 = (oc0 + 1 < Cout) ? bias[oc0+1] : 0.f;
#pragma unroll
        for (int j = 0; j < 2; j++) {
            F2U u; u.u = acc[a][j];
            size_t pix = (size_t)(ty0+prow)*W + tx0 + pcol + j;
            if (oc0 < Cout)
                out[((size_t)n*Cout + oc0)*HW + pix] = u.f.x + b0;
            if (oc0 + 1 < Cout)
                out[((size_t)n*Cout + oc0 + 1)*HW + pix] = u.f.y + b1;
        }
    }
}

// ---------------------------------------------------------------------------
// DCN main: bilinear-gather from concat(src0,src1)[128ch] with offsets om,
// GEMM with w(64,128,9), bias, activation.
// act=0: out = sigmoid(v)
// act=1: out = (1-z)*t + z*tanh(v)   (fused GRU combine)
// 2-oc FFMA2 packing (weights natural pairs, samples broadcast).
// smem 55296 B -> up to 4 blocks/SM. grid (144, nBranch, NB).
// ---------------------------------------------------------------------------
struct DcnArgs {
    const float* src0[2];
    const float* src1[2];
    const float* om[2];
    const float* wgt[2];
    const float* bias[2];
    float*       out[2];
    const float* zbuf[2];
    const float* tbuf[2];
};

#define DCN_SMEM 55296
extern __shared__ float dynsmem[];

__global__ __launch_bounds__(256)
void dcn_kernel(DcnArgs args, int act)
{
    float* sWgt = dynsmem;                    // 2304 f
    int*   sOff = (int*)(dynsmem + 2304);     // 2304 i
    float* sS   = dynsmem + 4608;             // 4608 f (72 x 64)
    float* sWt  = dynsmem + 9216;             // 4608 f (72 x 64)

    const int tile   = blockIdx.x;
    const int branch = blockIdx.y;
    const int n      = blockIdx.z;
    const int ty0  = (tile / 12) * 8;
    const int tx0  = (tile % 12) * 8;
    const int tid  = threadIdx.x;

    const float* __restrict__ src0 = args.src0[branch];
    const float* __restrict__ src1 = args.src1[branch];
    const float* __restrict__ om   = args.om[branch];
    const float* __restrict__ wgt  = args.wgt[branch];
    const float* __restrict__ bias = args.bias[branch];
    float*       __restrict__ out  = args.out[branch];

    // ---- precompute per-(k,px) clamped corner offsets + (bilinear*mask) wgts
    for (int idx = tid; idx < 576; idx += 256) {
        int k = idx >> 6, p = idx & 63;
        int py = ty0 + (p >> 3), px = tx0 + (p & 7);
        int pix = py*W + px;
        float dy = om[((size_t)n*27 + k     )*HW + pix];
        float dx = om[((size_t)n*27 + 9  + k)*HW + pix];
        float mv = om[((size_t)n*27 + 18 + k)*HW + pix];
        float m  = 1.f / (1.f + __expf(-mv));
        float fy = (float)(py + (k/3) - 1) + dy;
        float fx = (float)(px + (k%3) - 1) + dx;
        float y0f = floorf(fy), x0f = floorf(fx);
        float wy = fy - y0f, wx = fx - x0f;
        y0f = fmaxf(fminf(y0f, 1.0e4f), -1.0e4f);
        x0f = fmaxf(fminf(x0f, 1.0e4f), -1.0e4f);
        int iy0 = (int)y0f, ix0 = (int)x0f;
        int iy1 = iy0 + 1,  ix1 = ix0 + 1;
        bool vy0 = (unsigned)iy0 < H, vy1 = (unsigned)iy1 < H;
        bool vx0 = (unsigned)ix0 < W, vx1 = (unsigned)ix1 < W;
        int cy0 = min(max(iy0,0),H-1), cy1 = min(max(iy1,0),H-1);
        int cx0 = min(max(ix0,0),W-1), cx1 = min(max(ix1,0),W-1);
        int b = idx << 2;
        sOff[b+0] = cy0*W + cx0;  sWgt[b+0] = (vy0 && vx0) ? (1.f-wy)*(1.f-wx)*m : 0.f;
        sOff[b+1] = cy0*W + cx1;  sWgt[b+1] = (vy0 && vx1) ? (1.f-wy)*wx*m       : 0.f;
        sOff[b+2] = cy1*W + cx0;  sWgt[b+2] = (vy1 && vx0) ? wy*(1.f-wx)*m       : 0.f;
        sOff[b+3] = cy1*W + cx1;  sWgt[b+3] = (vy1 && vx1) ? wy*wx*m             : 0.f;
    }
    __syncthreads();

    const int ocg = tid >> 4;   // 0..15 (4 oc each)
    const int pxg = tid & 15;   // 0..15 (4 px each)
    ull acc[2][4];              // oc-pair a x px j
#pragma unroll
    for (int a = 0; a < 2; a++)
#pragma unroll
        for (int j = 0; j < 4; j++) acc[a][j] = 0ull;

    for (int ch0 = 0; ch0 < 128; ch0 += 8) {
        // stage gathered samples: sS[(cl*9+k)*64 + p]
        for (int idx = tid; idx < 4608; idx += 256) {
            int cl = idx / 576;
            int kp = idx % 576;
            int c  = ch0 + cl;
            const float* sp = (c < 64) ? (src0 + ((size_t)n*64 + c   )*HW)
                                       : (src1 + ((size_t)n*64 + c-64)*HW);
            int b = kp << 2;
            float v = sWgt[b+0] * __ldg(sp + sOff[b+0])
                    + sWgt[b+1] * __ldg(sp + sOff[b+1])
                    + sWgt[b+2] * __ldg(sp + sOff[b+2])
                    + sWgt[b+3] * __ldg(sp + sOff[b+3]);
            sS[idx] = v;
        }
        // stage weights: sWt[(cl*9+k)*64 + oc]
        for (int idx = tid; idx < 4608; idx += 256) {
            int kk = idx >> 6;
            int oc = idx & 63;
            int cl = kk / 9, k = kk % 9;
            sWt[idx] = __ldg(&wgt[((size_t)oc*128 + ch0 + cl)*9 + k]);
        }
        __syncthreads();
#pragma unroll 4
        for (int kk = 0; kk < 72; kk++) {
            const ull* w2 = reinterpret_cast<const ull*>(&sWt[kk*64 + (ocg<<2)]);
            ull w20 = w2[0], w21 = w2[1];
            const float4 s4 = *reinterpret_cast<const float4*>(&sS[kk*64 + (pxg<<2)]);
            ull s0 = bcast2(s4.x), s1 = bcast2(s4.y);
            ull s2 = bcast2(s4.z), s3 = bcast2(s4.w);
            ffma2(acc[0][0], w20, s0); ffma2(acc[1][0], w21, s0);
            ffma2(acc[0][1], w20, s1); ffma2(acc[1][1], w21, s1);
            ffma2(acc[0][2], w20, s2); ffma2(acc[1][2], w21, s2);
            ffma2(acc[0][3], w20, s3); ffma2(acc[1][3], w21, s3);
        }
        __syncthreads();
    }

    const int p0 = pxg << 2;
    const int oy = ty0 + (p0 >> 3);
    const int ox = tx0 + (p0 & 7);
#pragma unroll
    for (int a = 0; a < 2; a++) {
        int oc0 = (ocg<<2) + 2*a;
        float b0 = bias[oc0], b1 = bias[oc0+1];
        size_t base0 = ((size_t)n*64 + oc0)*HW + (size_t)oy*W + ox;
        size_t base1 = base0 + HW;
#pragma unroll
        for (int j = 0; j < 4; j++) {
            F2U u; u.u = acc[a][j];
            float v0 = u.f.x + b0, v1 = u.f.y + b1;
            if (act == 0) {
                out[base0 + j] = 1.f / (1.f + __expf(-v0));
                out[base1 + j] = 1.f / (1.f + __expf(-v1));
            } else {
                const float* zbuf = args.zbuf[branch];
                const float* tbuf = args.tbuf[branch];
                float z0 = zbuf[base0 + j], z1 = zbuf[base1 + j];
                out[base0 + j] = (1.f - z0) * tbuf[base0 + j] + z0 * tanhf(v0);
                out[base1 + j] = (1.f - z1) * tbuf[base1 + j] + z1 * tanhf(v1);
            }
        }
    }
}

// ---------------------------------------------------------------------------
// NCF: 49-tap (r=3, dil=2) correlation softmax-attention sample.
// Block 256 threads = 64 pixels x 4 channel-groups (16 ch each).
// grid (288, nBranch).
// ---------------------------------------------------------------------------
struct NcfArgs {
    const float* f1[2];
    const float* f2[2];
    float*       out[2];
};

__global__ void ncf_kernel(NcfArgs args)
{
    const int branch = blockIdx.y;
    const float* __restrict__ f1   = args.f1[branch];
    const float* __restrict__ f2   = args.f2[branch];
    float*       __restrict__ rout = args.out[branch];

    const int tid = threadIdx.x;
    const int cg  = tid & 3;
    const int pl  = tid >> 2;
    const int gp  = blockIdx.x * 64 + pl;   // 0 .. N*HW-1
    const int n   = gp / HW;
    const int pix = gp % HW;
    const int y   = pix / W, x = pix % W;

    unsigned long long vmask = 0ull;
#pragma unroll
    for (int k = 0; k < 49; k++) {
        int yy = y + (k/7)*2 - 6;
        int xx = x + (k%7)*2 - 6;
        if ((unsigned)yy < H && (unsigned)xx < W) vmask |= (1ull << k);
    }

    float corr[49];
#pragma unroll
    for (int k = 0; k < 49; k++) corr[k] = 0.f;

    const float* f1b = f1 + (size_t)n*64*HW + pix;
    const float* f2b = f2 + (size_t)n*64*HW + pix;

#pragma unroll 1
    for (int ci = 0; ci < 16; ci++) {
        int c = cg*16 + ci;
        float a = f1b[(size_t)c*HW];
        const float* fp = f2b + (size_t)c*HW;
#pragma unroll
        for (int k = 0; k < 49; k++) {
            int off = ((k/7)*2 - 6)*W + (k%7)*2 - 6;
            float v = ((vmask >> k) & 1ull) ? __ldg(fp + off) : 0.f;
            corr[k] = fmaf(a, v, corr[k]);
        }
    }
#pragma unroll
    for (int k = 0; k < 49; k++) {
        corr[k] += __shfl_xor_sync(0xffffffffu, corr[k], 1);
        corr[k] += __shfl_xor_sync(0xffffffffu, corr[k], 2);
        corr[k] *= 0.125f;   // 1/sqrt(64)
    }
    float mx = corr[0];
#pragma unroll
    for (int k = 1; k < 49; k++) mx = fmaxf(mx, corr[k]);
    float s = 0.f;
#pragma unroll
    for (int k = 0; k < 49; k++) { corr[k] = __expf(corr[k] - mx); s += corr[k]; }
    float inv = 1.f / s;
#pragma unroll
    for (int k = 0; k < 49; k++) corr[k] *= inv;

#pragma unroll 1
    for (int ci = 0; ci < 16; ci++) {
        int c = cg*16 + ci;
        const float* fp = f2b + (size_t)c*HW;
        float av = 0.f;
#pragma unroll
        for (int k = 0; k < 49; k++) {
            int off = ((k/7)*2 - 6)*W + (k%7)*2 - 6;
            float v = ((vmask >> k) & 1ull) ? __ldg(fp + off) : 0.f;
            av = fmaf(corr[k], v, av);
        }
        rout[((size_t)n*64 + c)*HW + pix] = av;
    }
}

// ---------------------------------------------------------------------------
extern "C" void kernel_launch(void* const* d_in, const int* in_sizes, int n_in,
                              void* d_out, int out_size)
{
    const float* X    = (const float*)d_in[0];
    const float* T    = (const float*)d_in[1];
    const float* Wi   = (const float*)d_in[2];
    const float* Bi   = (const float*)d_in[3];
    const float* Wo   = (const float*)d_in[4];
    const float* Bo   = (const float*)d_in[5];
    const float* EZW  = (const float*)d_in[6];
    const float* EZB  = (const float*)d_in[7];
    const float* EZOW = (const float*)d_in[8];
    const float* EZOB = (const float*)d_in[9];
    const float* EHW  = (const float*)d_in[10];
    const float* EHB  = (const float*)d_in[11];
    const float* EHOW = (const float*)d_in[12];
    const float* EHOB = (const float*)d_in[13];
    const float* UZW  = (const float*)d_in[14];
    const float* UZB  = (const float*)d_in[15];
    const float* UZOW = (const float*)d_in[16];
    const float* UZOB = (const float*)d_in[17];
    const float* UHW  = (const float*)d_in[18];
    const float* UHB  = (const float*)d_in[19];
    const float* UHOW = (const float*)d_in[20];
    const float* UHOB = (const float*)d_in[21];

    float* out  = (float*)d_out;
    float* newt = out + (size_t)NB*CIN*HW;

    float *xh, *om0, *om1, *z0, *z1, *r0, *r1, *xe;
    cudaGetSymbolAddress((void**)&xh,  g_xh);
    cudaGetSymbolAddress((void**)&om0, g_om0);
    cudaGetSymbolAddress((void**)&om1, g_om1);
    cudaGetSymbolAddress((void**)&z0,  g_z0);
    cudaGetSymbolAddress((void**)&z1,  g_z1);
    cudaGetSymbolAddress((void**)&r0,  g_r0);
    cudaGetSymbolAddress((void**)&r1,  g_r1);
    cudaGetSymbolAddress((void**)&xe,  g_xe);

    cudaFuncSetAttribute(dcn_kernel,
                         cudaFuncAttributeMaxDynamicSharedMemorySize, DCN_SMEM);

    // L1: xh = conv_in(x)   (single branch, Cout=64 -> grid.y=2)
    {
        ConvArgs a = { {X,X},{X,X},{Wi,Wi},{Bi,Bi},{xh,xh} };
        conv3x3_kernel<<<dim3(144, 2, NB), 256>>>(a, CIN, CIN, CH);
    }
    // L2: offset conv z, BOTH branches (Cout=27 -> grid.y=1, grid.z=2*NB)
    // field order: src0[2]={T,xh}, src1[2]={xh,T}
    {
        ConvArgs a = { {T,xh},{xh,T},{EZOW,UZOW},{EZOB,UZOB},{om0,om1} };
        conv3x3_kernel<<<dim3(144, 1, 2*NB), 256>>>(a, CH, 2*CH, 27);
    }
    // L3: dcn z, BOTH branches (sigmoid)
    {
        DcnArgs a = { {T,xh},{xh,T},{om0,om1},{EZW,UZW},{EZB,UZB},
                      {z0,z1},{nullptr,nullptr},{nullptr,nullptr} };
        dcn_kernel<<<dim3(144, 2, NB), 256, DCN_SMEM>>>(a, 0);
    }
    // L4: ncf, BOTH branches
    {
        NcfArgs a = { {xh,T},{T,xh},{r0,r1} };
        ncf_kernel<<<dim3(NB*HW/64, 2), 256>>>(a);
    }
    // L5: offset conv h, BOTH branches
    // FIXED: per-field arrays — src0[2]={r0,r1}, src1[2]={xh,T}
    {
        ConvArgs a = { {r0,r1},{xh,T},{EHOW,UHOW},{EHOB,UHOB},{om0,om1} };
        conv3x3_kernel<<<dim3(144, 1, 2*NB), 256>>>(a, CH, 2*CH, 27);
    }
    // L6: dcn h + fused GRU combine, BOTH branches
    // FIXED: src0[2]={r0,r1}, src1[2]={xh,T}
    {
        DcnArgs a = { {r0,r1},{xh,T},{om0,om1},{EHW,UHW},{EHB,UHB},
                      {xe,newt},{z0,z1},{xh,T} };
        dcn_kernel<<<dim3(144, 2, NB), 256, DCN_SMEM>>>(a, 1);
    }
    // L7: out = conv_out(x_enh)   (Cout=256 -> grid.y=8)
    {
        ConvArgs a = { {xe,xe},{xe,xe},{Wo,Wo},{Bo,Bo},{out,out} };
        conv3x3_kernel<<<dim3(144, 8, NB), 256>>>(a, CH, CH, CIN);
    }
}

// round 7
// speedup vs baseline: 1.8246x; 1.7565x over previous
#include <cuda_runtime.h>
#include <math.h>

#define H 96
#define W 96
#define HW 9216
#define NB 2
#define CIN 256
#define CH 64

typedef unsigned long long ull;
union F2U { ull u; float2 f; };

__device__ __forceinline__ ull bcast2(float a) {
    ull r; asm("mov.b64 %0,{%1,%1};" : "=l"(r) : "f"(a)); return r;
}
__device__ __forceinline__ void ffma2(ull& d, ull a, ull b) {
    asm("fma.rn.f32x2 %0,%1,%2,%0;" : "+l"(d) : "l"(a), "l"(b));
}

// ---------------- scratch (device globals; no allocation allowed) ----------
__device__ float g_xh [NB*CH*HW];
__device__ float g_om0[NB*27*HW];
__device__ float g_om1[NB*27*HW];
__device__ float g_z0 [NB*CH*HW];
__device__ float g_z1 [NB*CH*HW];
__device__ float g_r0 [NB*CH*HW];
__device__ float g_r1 [NB*CH*HW];
__device__ float g_xe [NB*CH*HW];
// pre-transposed weights: [c][k][oc_padded]
__device__ float g_cwT_in [256*9*64];
__device__ float g_cwT_out[64*9*256];
__device__ float g_owT    [4*128*9*32];
__device__ float g_dwT    [4*128*9*64];

// ---------------------------------------------------------------------------
// prep: wT[(c*9+k)*pad + oc] = (oc<Cout) ? w[((oc*Cin)+c)*9+k] : 0
// ---------------------------------------------------------------------------
struct PrepJobs {
    const float* src[10];
    float*       dst[10];
    int cin[10]; int cout[10]; int pad[10]; int total[10];
};

__global__ void prep_kernel(PrepJobs j)
{
    int job = blockIdx.y;
    int idx = blockIdx.x*256 + threadIdx.x;
    if (idx >= j.total[job]) return;
    int pad = j.pad[job];
    int oc  = idx % pad;
    int q   = idx / pad;
    int k   = q % 9;
    int c   = q / 9;
    float v = 0.f;
    if (oc < j.cout[job])
        v = j.src[job][((size_t)oc*j.cin[job] + c)*9 + k];
    j.dst[job][idx] = v;
}

// ---------------------------------------------------------------------------
// conv3x3, SAME, NCHW, input = concat(src0[C0], src1[Cin-C0]).
// OCT out-channels x 8x8 px per block (256 thr); thread = 4oc x P px (P=OCT/16).
// 8-channel chunks, double-buffered; weights pre-transposed -> float4 copies.
// ---------------------------------------------------------------------------
struct ConvArgs {
    const float* src0[2];
    const float* src1[2];
    const float* wT[2];    // [Cin][9][Cpad]
    const float* bias[2];
    float*       out[2];
};

template<int OCT>
__global__ __launch_bounds__(256)
void conv3x3_kernel(ConvArgs args, int C0, int Cin, int Cout, int Cpad)
{
    constexpr int P   = OCT/16;
    constexpr int PG  = 64/P;
    constexpr int WE4 = 8*9*OCT/4;            // float4 weights per 8-ch chunk
    constexpr int NWJ = (WE4 + 255)/256;
    __shared__ float sIn[2][800];
    __shared__ __align__(16) float sW[2][8*9*OCT];

    const int tile = blockIdx.x;
    const int ty0  = (tile/12)*8, tx0 = (tile%12)*8;
    const int branch = blockIdx.z / NB, n = blockIdx.z % NB;
    const int ocBase = blockIdx.y * OCT;
    const int tid = threadIdx.x;
    const int ocg = tid / PG, pxg = tid % PG;
    const int p0 = pxg*P, prow = p0>>3, pcol = p0&7;
    const int C1 = Cin - C0;

    const float* __restrict__ src0 = args.src0[branch];
    const float* __restrict__ src1 = args.src1[branch];
    const float* __restrict__ bias = args.bias[branch];
    float*       __restrict__ out  = args.out[branch];
    const float4* __restrict__ wT4 = (const float4*)args.wT[branch];
    const int Cp4 = Cpad >> 2;

    ull acc[2][P];
#pragma unroll
    for (int a = 0; a < 2; a++)
#pragma unroll
        for (int jj = 0; jj < P; jj++) acc[a][jj] = 0ull;

    float  rIn[4];
    float4 rW[NWJ];

    auto loadChunk = [&](int c0) {
#pragma unroll
        for (int j = 0; j < 4; j++) {
            int idx = tid + j*256;
            float v = 0.f;
            if (idx < 800) {
                int cc = idx/100, rem = idx%100;
                int r = rem/10, cl = rem%10;
                int gy = ty0+r-1, gx = tx0+cl-1;
                if ((unsigned)gy < H && (unsigned)gx < W) {
                    int ch = c0+cc;
                    const float* sp = (ch < C0)
                        ? src0 + ((size_t)n*C0 + ch)*HW
                        : src1 + ((size_t)n*C1 + (ch-C0))*HW;
                    v = __ldg(sp + gy*W + gx);
                }
            }
            rIn[j] = v;
        }
        size_t wbase = (size_t)(c0*9)*Cp4 + (ocBase>>2);
#pragma unroll
        for (int j = 0; j < NWJ; j++) {
            int idx4 = tid + j*256;
            if (idx4 < WE4) {
                int q  = idx4 / (OCT/4);
                int o4 = idx4 & (OCT/4 - 1);
                rW[j] = wT4[wbase + (size_t)q*Cp4 + o4];
            }
        }
    };
    auto storeChunk = [&](int buf) {
#pragma unroll
        for (int j = 0; j < 4; j++) {
            int idx = tid + j*256;
            if (idx < 800) sIn[buf][idx] = rIn[j];
        }
#pragma unroll
        for (int j = 0; j < NWJ; j++) {
            int idx4 = tid + j*256;
            if (idx4 < WE4) ((float4*)sW[buf])[idx4] = rW[j];
        }
    };

    loadChunk(0);
    storeChunk(0);
    __syncthreads();

    int cur = 0;
    for (int c0 = 0; c0 < Cin; c0 += 8) {
        bool more = (c0 + 8 < Cin);
        if (more) loadChunk(c0 + 8);
#pragma unroll
        for (int cc = 0; cc < 8; cc++) {
#pragma unroll
            for (int ky = 0; ky < 3; ky++) {
                const float* irow = &sIn[cur][cc*100 + (prow+ky)*10 + pcol];
                ull ip[P+2];
#pragma unroll
                for (int t = 0; t < P+2; t++) ip[t] = bcast2(irow[t]);
#pragma unroll
                for (int kx = 0; kx < 3; kx++) {
                    const ull* w2 = (const ull*)&sW[cur][(cc*9+ky*3+kx)*OCT + (ocg<<2)];
                    ull w20 = w2[0], w21 = w2[1];
#pragma unroll
                    for (int jj = 0; jj < P; jj++) {
                        ffma2(acc[0][jj], w20, ip[kx+jj]);
                        ffma2(acc[1][jj], w21, ip[kx+jj]);
                    }
                }
            }
        }
        if (more) storeChunk(cur ^ 1);
        __syncthreads();
        cur ^= 1;
    }

#pragma unroll
    for (int a = 0; a < 2; a++) {
        int oc0 = ocBase + (ocg<<2) + 2*a;
        float b0 = (oc0     < Cout) ? bias[oc0]   : 0.f;
        float b1 = (oc0 + 1 < Cout) ? bias[oc0+1] : 0.f;
#pragma unroll
        for (int jj = 0; jj < P; jj++) {
            F2U u; u.u = acc[a][jj];
            size_t pix = (size_t)(ty0+prow)*W + tx0 + pcol + jj;
            if (oc0 < Cout)
                out[((size_t)n*Cout + oc0)*HW + pix] = u.f.x + b0;
            if (oc0 + 1 < Cout)
                out[((size_t)n*Cout + oc0 + 1)*HW + pix] = u.f.y + b1;
        }
    }
}

// ---------------------------------------------------------------------------
// DCN: bilinear gather + GEMM w(64,128,9) + bias + activation.
// act=0: sigmoid; act=1: (1-z)*t + z*tanh(v) (fused GRU combine).
// Pair-major gather (offsets loaded once per (k,px), 8 channels by ptr-incr);
// weights pre-transposed -> contiguous float4 copy.
// ---------------------------------------------------------------------------
struct DcnArgs {
    const float* src0[2];
    const float* src1[2];
    const float* om[2];
    const float* wT[2];    // [128][9][64]
    const float* bias[2];
    float*       out[2];
    const float* zbuf[2];
    const float* tbuf[2];
};

#define DCN_SMEM 55296
extern __shared__ float dynsmem[];

__global__ __launch_bounds__(256)
void dcn_kernel(DcnArgs args, int act)
{
    float* sWgt = dynsmem;                    // 2304 f
    int*   sOff = (int*)(dynsmem + 2304);     // 2304 i
    float* sS   = dynsmem + 4608;             // 4608 f (8cl x 576 kp)
    float* sWt  = dynsmem + 9216;             // 4608 f (72 x 64)

    const int tile   = blockIdx.x;
    const int branch = blockIdx.y;
    const int n      = blockIdx.z;
    const int ty0 = (tile/12)*8, tx0 = (tile%12)*8;
    const int tid = threadIdx.x;

    const float* __restrict__ src0 = args.src0[branch];
    const float* __restrict__ src1 = args.src1[branch];
    const float* __restrict__ om   = args.om[branch];
    const float* __restrict__ bias = args.bias[branch];
    float*       __restrict__ out  = args.out[branch];
    const float4* __restrict__ wT4 = (const float4*)args.wT[branch];

    // ---- precompute per-(k,px) clamped corner offsets + (bilinear*mask) wgts
    for (int idx = tid; idx < 576; idx += 256) {
        int k = idx >> 6, p = idx & 63;
        int py = ty0 + (p >> 3), px = tx0 + (p & 7);
        int pix = py*W + px;
        float dy = om[((size_t)n*27 + k     )*HW + pix];
        float dx = om[((size_t)n*27 + 9  + k)*HW + pix];
        float mv = om[((size_t)n*27 + 18 + k)*HW + pix];
        float m  = 1.f / (1.f + __expf(-mv));
        float fy = (float)(py + (k/3) - 1) + dy;
        float fx = (float)(px + (k%3) - 1) + dx;
        float y0f = floorf(fy), x0f = floorf(fx);
        float wy = fy - y0f, wx = fx - x0f;
        y0f = fmaxf(fminf(y0f, 1.0e4f), -1.0e4f);
        x0f = fmaxf(fminf(x0f, 1.0e4f), -1.0e4f);
        int iy0 = (int)y0f, ix0 = (int)x0f;
        int iy1 = iy0 + 1,  ix1 = ix0 + 1;
        bool vy0 = (unsigned)iy0 < H, vy1 = (unsigned)iy1 < H;
        bool vx0 = (unsigned)ix0 < W, vx1 = (unsigned)ix1 < W;
        int cy0 = min(max(iy0,0),H-1), cy1 = min(max(iy1,0),H-1);
        int cx0 = min(max(ix0,0),W-1), cx1 = min(max(ix1,0),W-1);
        int b = idx << 2;
        sOff[b+0] = cy0*W + cx0;  sWgt[b+0] = (vy0 && vx0) ? (1.f-wy)*(1.f-wx)*m : 0.f;
        sOff[b+1] = cy0*W + cx1;  sWgt[b+1] = (vy0 && vx1) ? (1.f-wy)*wx*m       : 0.f;
        sOff[b+2] = cy1*W + cx0;  sWgt[b+2] = (vy1 && vx0) ? wy*(1.f-wx)*m       : 0.f;
        sOff[b+3] = cy1*W + cx1;  sWgt[b+3] = (vy1 && vx1) ? wy*wx*m             : 0.f;
    }
    __syncthreads();

    const int ocg = tid >> 4;   // 0..15 (4 oc each)
    const int pxg = tid & 15;   // 0..15 (4 px each)
    ull acc[2][4];
#pragma unroll
    for (int a = 0; a < 2; a++)
#pragma unroll
        for (int jj = 0; jj < 4; jj++) acc[a][jj] = 0ull;

    for (int ch0 = 0; ch0 < 128; ch0 += 8) {
        // channel-chunk base (chunks never straddle the 64-ch boundary)
        const float* base = (ch0 < 64)
            ? src0 + ((size_t)n*64 + ch0)*HW
            : src1 + ((size_t)n*64 + (ch0-64))*HW;

        // gather: offsets/weights loaded once per (k,px), 8 channels ptr-incr
        for (int pair = tid; pair < 576; pair += 256) {
            const float4 wq = *(const float4*)&sWgt[pair<<2];
            const int4   oq = *(const int4*)  &sOff[pair<<2];
            const float* pa = base + oq.x;
            const float* pb = base + oq.y;
            const float* pc = base + oq.z;
            const float* pd = base + oq.w;
            float* sdst = sS + pair;
#pragma unroll
            for (int cl = 0; cl < 8; cl++) {
                float v = wq.x * __ldg(pa) + wq.y * __ldg(pb)
                        + wq.z * __ldg(pc) + wq.w * __ldg(pd);
                sdst[cl*576] = v;
                pa += HW; pb += HW; pc += HW; pd += HW;
            }
        }
        // weights: contiguous chunk [ch0..ch0+8)[9][64] = 1152 float4
        {
            const float4* ws = wT4 + (size_t)ch0*144;   // 576 floats per ch
#pragma unroll
            for (int j = 0; j < 5; j++) {
                int idx4 = tid + j*256;
                if (idx4 < 1152) ((float4*)sWt)[idx4] = ws[idx4];
            }
        }
        __syncthreads();
#pragma unroll 4
        for (int kk = 0; kk < 72; kk++) {
            const ull* w2 = (const ull*)&sWt[kk*64 + (ocg<<2)];
            ull w20 = w2[0], w21 = w2[1];
            // sS layout: [cl][kp] with kp=(k*64+p); kk=cl*9+k
            const int cl = kk/9, k = kk - cl*9;
            const float4 s4 = *(const float4*)&sS[cl*576 + k*64 + (pxg<<2)];
            ull s0 = bcast2(s4.x), s1 = bcast2(s4.y);
            ull s2 = bcast2(s4.z), s3 = bcast2(s4.w);
            ffma2(acc[0][0], w20, s0); ffma2(acc[1][0], w21, s0);
            ffma2(acc[0][1], w20, s1); ffma2(acc[1][1], w21, s1);
            ffma2(acc[0][2], w20, s2); ffma2(acc[1][2], w21, s2);
            ffma2(acc[0][3], w20, s3); ffma2(acc[1][3], w21, s3);
        }
        __syncthreads();
    }

    const int p0 = pxg << 2;
    const int oy = ty0 + (p0 >> 3);
    const int ox = tx0 + (p0 & 7);
#pragma unroll
    for (int a = 0; a < 2; a++) {
        int oc0 = (ocg<<2) + 2*a;
        float b0 = bias[oc0], b1 = bias[oc0+1];
        size_t base0 = ((size_t)n*64 + oc0)*HW + (size_t)oy*W + ox;
        size_t base1 = base0 + HW;
#pragma unroll
        for (int jj = 0; jj < 4; jj++) {
            F2U u; u.u = acc[a][jj];
            float v0 = u.f.x + b0, v1 = u.f.y + b1;
            if (act == 0) {
                out[base0 + jj] = 1.f / (1.f + __expf(-v0));
                out[base1 + jj] = 1.f / (1.f + __expf(-v1));
            } else {
                const float* zbuf = args.zbuf[branch];
                const float* tbuf = args.tbuf[branch];
                float z0 = zbuf[base0 + jj], z1 = zbuf[base1 + jj];
                out[base0 + jj] = (1.f - z0) * tbuf[base0 + jj] + z0 * tanhf(v0);
                out[base1 + jj] = (1.f - z1) * tbuf[base1 + jj] + z1 * tanhf(v1);
            }
        }
    }
}

// ---------------------------------------------------------------------------
// NCF: 49-tap (r=3, dil=2) correlation softmax-attention sample.
// Interior pixels (77%) take an unguarded constant-offset fast path.
// ---------------------------------------------------------------------------
struct NcfArgs {
    const float* f1[2];
    const float* f2[2];
    float*       out[2];
};

#define NCF_OFF(k) ((((k)/7)*2 - 6)*W + ((k)%7)*2 - 6)

__global__ __launch_bounds__(256)
void ncf_kernel(NcfArgs args)
{
    const int branch = blockIdx.y;
    const float* __restrict__ f1   = args.f1[branch];
    const float* __restrict__ f2   = args.f2[branch];
    float*       __restrict__ rout = args.out[branch];

    const int tid = threadIdx.x;
    const int cg  = tid & 3;
    const int pl  = tid >> 2;
    const int gp  = blockIdx.x * 64 + pl;
    const int n   = gp / HW;
    const int pix = gp % HW;
    const int y   = pix / W, x = pix % W;
    const bool safe = (y >= 6) && (y < H-6) && (x >= 6) && (x < W-6);

    float corr[49];
#pragma unroll
    for (int k = 0; k < 49; k++) corr[k] = 0.f;

    const float* f1b = f1 + (size_t)n*64*HW + pix;
    const float* f2b = f2 + (size_t)n*64*HW + pix;

    unsigned long long vmask = 0ull;
    if (safe) {
#pragma unroll 1
        for (int ci = 0; ci < 16; ci++) {
            int c = cg*16 + ci;
            float a = f1b[(size_t)c*HW];
            const float* fp = f2b + (size_t)c*HW;
#pragma unroll
            for (int k = 0; k < 49; k++)
                corr[k] = fmaf(a, __ldg(fp + NCF_OFF(k)), corr[k]);
        }
    } else {
#pragma unroll
        for (int k = 0; k < 49; k++) {
            int yy = y + (k/7)*2 - 6;
            int xx = x + (k%7)*2 - 6;
            if ((unsigned)yy < H && (unsigned)xx < W) vmask |= (1ull << k);
        }
#pragma unroll 1
        for (int ci = 0; ci < 16; ci++) {
            int c = cg*16 + ci;
            float a = f1b[(size_t)c*HW];
            const float* fp = f2b + (size_t)c*HW;
#pragma unroll
            for (int k = 0; k < 49; k++) {
                float v = ((vmask >> k) & 1ull) ? __ldg(fp + NCF_OFF(k)) : 0.f;
                corr[k] = fmaf(a, v, corr[k]);
            }
        }
    }
#pragma unroll
    for (int k = 0; k < 49; k++) {
        corr[k] += __shfl_xor_sync(0xffffffffu, corr[k], 1);
        corr[k] += __shfl_xor_sync(0xffffffffu, corr[k], 2);
        corr[k] *= 0.125f;   // 1/sqrt(64)
    }
    float mx = corr[0];
#pragma unroll
    for (int k = 1; k < 49; k++) mx = fmaxf(mx, corr[k]);
    float s = 0.f;
#pragma unroll
    for (int k = 0; k < 49; k++) { corr[k] = __expf(corr[k] - mx); s += corr[k]; }
    float inv = 1.f / s;
#pragma unroll
    for (int k = 0; k < 49; k++) corr[k] *= inv;

    if (safe) {
#pragma unroll 1
        for (int ci = 0; ci < 16; ci++) {
            int c = cg*16 + ci;
            const float* fp = f2b + (size_t)c*HW;
            float av = 0.f;
#pragma unroll
            for (int k = 0; k < 49; k++)
                av = fmaf(corr[k], __ldg(fp + NCF_OFF(k)), av);
            rout[((size_t)n*64 + c)*HW + pix] = av;
        }
    } else {
#pragma unroll 1
        for (int ci = 0; ci < 16; ci++) {
            int c = cg*16 + ci;
            const float* fp = f2b + (size_t)c*HW;
            float av = 0.f;
#pragma unroll
            for (int k = 0; k < 49; k++) {
                float v = ((vmask >> k) & 1ull) ? __ldg(fp + NCF_OFF(k)) : 0.f;
                av = fmaf(corr[k], v, av);
            }
            rout[((size_t)n*64 + c)*HW + pix] = av;
        }
    }
}

// ---------------------------------------------------------------------------
extern "C" void kernel_launch(void* const* d_in, const int* in_sizes, int n_in,
                              void* d_out, int out_size)
{
    const float* X    = (const float*)d_in[0];
    const float* T    = (const float*)d_in[1];
    const float* Wi   = (const float*)d_in[2];
    const float* Bi   = (const float*)d_in[3];
    const float* Wo   = (const float*)d_in[4];
    const float* Bo   = (const float*)d_in[5];
    const float* EZW  = (const float*)d_in[6];
    const float* EZB  = (const float*)d_in[7];
    const float* EZOW = (const float*)d_in[8];
    const float* EZOB = (const float*)d_in[9];
    const float* EHW  = (const float*)d_in[10];
    const float* EHB  = (const float*)d_in[11];
    const float* EHOW = (const float*)d_in[12];
    const float* EHOB = (const float*)d_in[13];
    const float* UZW  = (const float*)d_in[14];
    const float* UZB  = (const float*)d_in[15];
    const float* UZOW = (const float*)d_in[16];
    const float* UZOB = (const float*)d_in[17];
    const float* UHW  = (const float*)d_in[18];
    const float* UHB  = (const float*)d_in[19];
    const float* UHOW = (const float*)d_in[20];
    const float* UHOB = (const float*)d_in[21];

    float* out  = (float*)d_out;
    float* newt = out + (size_t)NB*CIN*HW;

    float *xh, *om0, *om1, *z0, *z1, *r0, *r1, *xe;
    float *cwi, *cwo, *owt, *dwt;
    cudaGetSymbolAddress((void**)&xh,  g_xh);
    cudaGetSymbolAddress((void**)&om0, g_om0);
    cudaGetSymbolAddress((void**)&om1, g_om1);
    cudaGetSymbolAddress((void**)&z0,  g_z0);
    cudaGetSymbolAddress((void**)&z1,  g_z1);
    cudaGetSymbolAddress((void**)&r0,  g_r0);
    cudaGetSymbolAddress((void**)&r1,  g_r1);
    cudaGetSymbolAddress((void**)&xe,  g_xe);
    cudaGetSymbolAddress((void**)&cwi, g_cwT_in);
    cudaGetSymbolAddress((void**)&cwo, g_cwT_out);
    cudaGetSymbolAddress((void**)&owt, g_owT);
    cudaGetSymbolAddress((void**)&dwt, g_dwT);

    float* owT0 = owt;               // EZ offset
    float* owT1 = owt + 1*36864;     // UZ offset
    float* owT2 = owt + 2*36864;     // EH offset
    float* owT3 = owt + 3*36864;     // UH offset
    float* dwT0 = dwt;               // EZ dcn
    float* dwT1 = dwt + 1*73728;     // EH dcn
    float* dwT2 = dwt + 2*73728;     // UZ dcn
    float* dwT3 = dwt + 3*73728;     // UH dcn

    cudaFuncSetAttribute(dcn_kernel,
                         cudaFuncAttributeMaxDynamicSharedMemorySize, DCN_SMEM);

    // L0: weight transposition (tiny)
    {
        PrepJobs pj;
        const float* srcs[10] = {Wi, Wo, EZOW, UZOW, EHOW, UHOW, EZW, EHW, UZW, UHW};
        float* dsts[10] = {cwi, cwo, owT0, owT1, owT2, owT3, dwT0, dwT1, dwT2, dwT3};
        int cins [10] = {256, 64, 128, 128, 128, 128, 128, 128, 128, 128};
        int couts[10] = {64, 256, 27, 27, 27, 27, 64, 64, 64, 64};
        int pads [10] = {64, 256, 32, 32, 32, 32, 64, 64, 64, 64};
        for (int i = 0; i < 10; i++) {
            pj.src[i] = srcs[i]; pj.dst[i] = dsts[i];
            pj.cin[i] = cins[i]; pj.cout[i] = couts[i]; pj.pad[i] = pads[i];
            pj.total[i] = cins[i]*9*pads[i];
        }
        prep_kernel<<<dim3(576, 10), 256>>>(pj);
    }

    // L1: xh = conv_in(x)  (OCT=64, Cout=64)
    {
        ConvArgs a = { {X,X},{X,X},{cwi,cwi},{Bi,Bi},{xh,xh} };
        conv3x3_kernel<64><<<dim3(144, 1, NB), 256>>>(a, CIN, CIN, CH, 64);
    }
    // L2: offset conv z, both branches (OCT=32, Cout=27)
    {
        ConvArgs a = { {T,xh},{xh,T},{owT0,owT1},{EZOB,UZOB},{om0,om1} };
        conv3x3_kernel<32><<<dim3(144, 1, 2*NB), 256>>>(a, CH, 2*CH, 27, 32);
    }
    // L3: dcn z, both branches (sigmoid)
    {
        DcnArgs a = { {T,xh},{xh,T},{om0,om1},{dwT0,dwT2},{EZB,UZB},
                      {z0,z1},{nullptr,nullptr},{nullptr,nullptr} };
        dcn_kernel<<<dim3(144, 2, NB), 256, DCN_SMEM>>>(a, 0);
    }
    // L4: ncf, both branches
    {
        NcfArgs a = { {xh,T},{T,xh},{r0,r1} };
        ncf_kernel<<<dim3(NB*HW/64, 2), 256>>>(a);
    }
    // L5: offset conv h, both branches
    {
        ConvArgs a = { {r0,r1},{xh,T},{owT2,owT3},{EHOB,UHOB},{om0,om1} };
        conv3x3_kernel<32><<<dim3(144, 1, 2*NB), 256>>>(a, CH, 2*CH, 27, 32);
    }
    // L6: dcn h + fused GRU combine, both branches
    {
        DcnArgs a = { {r0,r1},{xh,T},{om0,om1},{dwT1,dwT3},{EHB,UHB},
                      {xe,newt},{z0,z1},{xh,T} };
        dcn_kernel<<<dim3(144, 2, NB), 256, DCN_SMEM>>>(a, 1);
    }
    // L7: out = conv_out(x_enh)  (OCT=64, Cout=256)
    {
        ConvArgs a = { {xe,xe},{xe,xe},{cwo,cwo},{Bo,Bo},{out,out} };
        conv3x3_kernel<64><<<dim3(144, 4, NB), 256>>>(a, CH, CH, CIN, 256);
    }
}

// round 8
// speedup vs baseline: 1.9506x; 1.0691x over previous
#include <cuda_runtime.h>
#include <math.h>

#define H 96
#define W 96
#define HW 9216
#define NB 2
#define CIN 256
#define CH 64

typedef unsigned long long ull;
union F2U { ull u; float2 f; };

__device__ __forceinline__ ull bcast2(float a) {
    ull r; asm("mov.b64 %0,{%1,%1};" : "=l"(r) : "f"(a)); return r;
}
__device__ __forceinline__ void ffma2(ull& d, ull a, ull b) {
    asm("fma.rn.f32x2 %0,%1,%2,%0;" : "+l"(d) : "l"(a), "l"(b));
}

// ---------------- scratch (device globals; no allocation allowed) ----------
__device__ float g_xh [NB*CH*HW];
__device__ float g_om0[NB*27*HW];
__device__ float g_om1[NB*27*HW];
__device__ float g_z0 [NB*CH*HW];
__device__ float g_z1 [NB*CH*HW];
__device__ float g_r0 [NB*CH*HW];
__device__ float g_r1 [NB*CH*HW];
__device__ float g_xe [NB*CH*HW];
// pre-transposed weights: [c][k][oc_padded]
__device__ float g_cwT_in [256*9*64];
__device__ float g_cwT_out[64*9*256];
__device__ float g_owT    [4*128*9*32];
__device__ float g_dwT    [4*128*9*64];

// ---------------------------------------------------------------------------
// prep: wT[(c*9+k)*pad + oc] = (oc<Cout) ? w[((oc*Cin)+c)*9+k] : 0
// ---------------------------------------------------------------------------
struct PrepJobs {
    const float* src[10];
    float*       dst[10];
    int cin[10]; int cout[10]; int pad[10]; int total[10];
};

__global__ void prep_kernel(PrepJobs j)
{
    int job = blockIdx.y;
    int idx = blockIdx.x*256 + threadIdx.x;
    if (idx >= j.total[job]) return;
    int pad = j.pad[job];
    int oc  = idx % pad;
    int q   = idx / pad;
    int k   = q % 9;
    int c   = q / 9;
    float v = 0.f;
    if (oc < j.cout[job])
        v = j.src[job][((size_t)oc*j.cin[job] + c)*9 + k];
    j.dst[job][idx] = v;
}

// ---------------------------------------------------------------------------
// conv3x3, SAME, NCHW, input = concat(src0[C0], src1[Cin-C0]).
// OCT out-channels x 8x8 px per block (256 thr); thread = 4oc x P px (P=OCT/16).
// 8-channel chunks, double-buffered; weights pre-transposed -> float4 copies.
// ---------------------------------------------------------------------------
struct ConvArgs {
    const float* src0[2];
    const float* src1[2];
    const float* wT[2];    // [Cin][9][Cpad]
    const float* bias[2];
    float*       out[2];
};

template<int OCT>
__global__ __launch_bounds__(256)
void conv3x3_kernel(ConvArgs args, int C0, int Cin, int Cout, int Cpad)
{
    constexpr int P   = OCT/16;
    constexpr int PG  = 64/P;
    constexpr int WE4 = 8*9*OCT/4;            // float4 weights per 8-ch chunk
    constexpr int NWJ = (WE4 + 255)/256;
    __shared__ float sIn[2][800];
    __shared__ __align__(16) float sW[2][8*9*OCT];

    const int tile = blockIdx.x;
    const int ty0  = (tile/12)*8, tx0 = (tile%12)*8;
    const int branch = blockIdx.z / NB, n = blockIdx.z % NB;
    const int ocBase = blockIdx.y * OCT;
    const int tid = threadIdx.x;
    const int ocg = tid / PG, pxg = tid % PG;
    const int p0 = pxg*P, prow = p0>>3, pcol = p0&7;
    const int C1 = Cin - C0;

    const float* __restrict__ src0 = args.src0[branch];
    const float* __restrict__ src1 = args.src1[branch];
    const float* __restrict__ bias = args.bias[branch];
    float*       __restrict__ out  = args.out[branch];
    const float4* __restrict__ wT4 = (const float4*)args.wT[branch];
    const int Cp4 = Cpad >> 2;

    ull acc[2][P];
#pragma unroll
    for (int a = 0; a < 2; a++)
#pragma unroll
        for (int jj = 0; jj < P; jj++) acc[a][jj] = 0ull;

    float  rIn[4];
    float4 rW[NWJ];

    auto loadChunk = [&](int c0) {
#pragma unroll
        for (int j = 0; j < 4; j++) {
            int idx = tid + j*256;
            float v = 0.f;
            if (idx < 800) {
                int cc = idx/100, rem = idx%100;
                int r = rem/10, cl = rem%10;
                int gy = ty0+r-1, gx = tx0+cl-1;
                if ((unsigned)gy < H && (unsigned)gx < W) {
                    int ch = c0+cc;
                    const float* sp = (ch < C0)
                        ? src0 + ((size_t)n*C0 + ch)*HW
                        : src1 + ((size_t)n*C1 + (ch-C0))*HW;
                    v = __ldg(sp + gy*W + gx);
                }
            }
            rIn[j] = v;
        }
        size_t wbase = (size_t)(c0*9)*Cp4 + (ocBase>>2);
#pragma unroll
        for (int j = 0; j < NWJ; j++) {
            int idx4 = tid + j*256;
            if (idx4 < WE4) {
                int q  = idx4 / (OCT/4);
                int o4 = idx4 & (OCT/4 - 1);
                rW[j] = wT4[wbase + (size_t)q*Cp4 + o4];
            }
        }
    };
    auto storeChunk = [&](int buf) {
#pragma unroll
        for (int j = 0; j < 4; j++) {
            int idx = tid + j*256;
            if (idx < 800) sIn[buf][idx] = rIn[j];
        }
#pragma unroll
        for (int j = 0; j < NWJ; j++) {
            int idx4 = tid + j*256;
            if (idx4 < WE4) ((float4*)sW[buf])[idx4] = rW[j];
        }
    };

    loadChunk(0);
    storeChunk(0);
    __syncthreads();

    int cur = 0;
    for (int c0 = 0; c0 < Cin; c0 += 8) {
        bool more = (c0 + 8 < Cin);
        if (more) loadChunk(c0 + 8);
#pragma unroll
        for (int cc = 0; cc < 8; cc++) {
#pragma unroll
            for (int ky = 0; ky < 3; ky++) {
                const float* irow = &sIn[cur][cc*100 + (prow+ky)*10 + pcol];
                ull ip[P+2];
#pragma unroll
                for (int t = 0; t < P+2; t++) ip[t] = bcast2(irow[t]);
#pragma unroll
                for (int kx = 0; kx < 3; kx++) {
                    const ull* w2 = (const ull*)&sW[cur][(cc*9+ky*3+kx)*OCT + (ocg<<2)];
                    ull w20 = w2[0], w21 = w2[1];
#pragma unroll
                    for (int jj = 0; jj < P; jj++) {
                        ffma2(acc[0][jj], w20, ip[kx+jj]);
                        ffma2(acc[1][jj], w21, ip[kx+jj]);
                    }
                }
            }
        }
        if (more) storeChunk(cur ^ 1);
        __syncthreads();
        cur ^= 1;
    }

#pragma unroll
    for (int a = 0; a < 2; a++) {
        int oc0 = ocBase + (ocg<<2) + 2*a;
        float b0 = (oc0     < Cout) ? bias[oc0]   : 0.f;
        float b1 = (oc0 + 1 < Cout) ? bias[oc0+1] : 0.f;
#pragma unroll
        for (int jj = 0; jj < P; jj++) {
            F2U u; u.u = acc[a][jj];
            size_t pix = (size_t)(ty0+prow)*W + tx0 + pcol + jj;
            if (oc0 < Cout)
                out[((size_t)n*Cout + oc0)*HW + pix] = u.f.x + b0;
            if (oc0 + 1 < Cout)
                out[((size_t)n*Cout + oc0 + 1)*HW + pix] = u.f.y + b1;
        }
    }
}

// ---------------------------------------------------------------------------
// DCN: bilinear gather + GEMM w(64,128,9) + bias + activation.
// act=0: sigmoid; act=1: (1-z)*t + z*tanh(v) (fused GRU combine).
// Gather goes through a smem-staged 16x16 halo tile (8 channels/chunk):
// if all 4 clamped bilinear corners fall inside the staged region (precomputed
// per (tap,px) flag), read LDS; else fall back to scattered LDG. This moves
// the dominant L1tex wavefront traffic onto the smem crossbar.
// ---------------------------------------------------------------------------
struct DcnArgs {
    const float* src0[2];
    const float* src1[2];
    const float* om[2];
    const float* wT[2];    // [128][9][64]
    const float* bias[2];
    float*       out[2];
    const float* zbuf[2];
    const float* tbuf[2];
};

// smem layout (floats): sWgt 2304 | sOff 2304 | sFlag 576 | sTile 2176 |
//                       sS 4608 | sWt 4608   = 16576 floats = 66304 B
#define DCN_SMEM 66304
extern __shared__ float dynsmem[];

__global__ __launch_bounds__(256)
void dcn_kernel(DcnArgs args, int act)
{
    float* sWgt  = dynsmem;                    // 2304 f
    int*   sOff  = (int*)(dynsmem + 2304);     // 2304 i
    int*   sFlag = (int*)(dynsmem + 4608);     // 576 i
    float* sTile = dynsmem + 5184;             // 2176 f (8ch x 16x17)
    float* sS    = dynsmem + 7360;             // 4608 f (8cl x 576 kp)
    float* sWt   = dynsmem + 11968;            // 4608 f (72 x 64)

    const int tile   = blockIdx.x;
    const int branch = blockIdx.y;
    const int n      = blockIdx.z;
    const int ty0 = (tile/12)*8, tx0 = (tile%12)*8;
    const int ry0 = ty0 - 4,     rx0 = tx0 - 4;     // staged region origin
    const int tid = threadIdx.x;

    const float* __restrict__ src0 = args.src0[branch];
    const float* __restrict__ src1 = args.src1[branch];
    const float* __restrict__ om   = args.om[branch];
    const float* __restrict__ bias = args.bias[branch];
    float*       __restrict__ out  = args.out[branch];
    const float4* __restrict__ wT4 = (const float4*)args.wT[branch];

    // ---- precompute per-(k,px) corner offsets + (bilinear*mask) weights;
    //      local smem offsets when the 4 corners sit inside the staged region
    for (int idx = tid; idx < 576; idx += 256) {
        int k = idx >> 6, p = idx & 63;
        int py = ty0 + (p >> 3), px = tx0 + (p & 7);
        int pix = py*W + px;
        float dy = om[((size_t)n*27 + k     )*HW + pix];
        float dx = om[((size_t)n*27 + 9  + k)*HW + pix];
        float mv = om[((size_t)n*27 + 18 + k)*HW + pix];
        float m  = 1.f / (1.f + __expf(-mv));
        float fy = (float)(py + (k/3) - 1) + dy;
        float fx = (float)(px + (k%3) - 1) + dx;
        float y0f = floorf(fy), x0f = floorf(fx);
        float wy = fy - y0f, wx = fx - x0f;
        y0f = fmaxf(fminf(y0f, 1.0e4f), -1.0e4f);
        x0f = fmaxf(fminf(x0f, 1.0e4f), -1.0e4f);
        int iy0 = (int)y0f, ix0 = (int)x0f;
        int iy1 = iy0 + 1,  ix1 = ix0 + 1;
        bool vy0 = (unsigned)iy0 < H, vy1 = (unsigned)iy1 < H;
        bool vx0 = (unsigned)ix0 < W, vx1 = (unsigned)ix1 < W;
        int cy0 = min(max(iy0,0),H-1), cy1 = min(max(iy1,0),H-1);
        int cx0 = min(max(ix0,0),W-1), cx1 = min(max(ix1,0),W-1);
        int b = idx << 2;
        sWgt[b+0] = (vy0 && vx0) ? (1.f-wy)*(1.f-wx)*m : 0.f;
        sWgt[b+1] = (vy0 && vx1) ? (1.f-wy)*wx*m       : 0.f;
        sWgt[b+2] = (vy1 && vx0) ? wy*(1.f-wx)*m       : 0.f;
        sWgt[b+3] = (vy1 && vx1) ? wy*wx*m             : 0.f;
        bool inreg = (cy0 >= ry0) && (cy1 < ry0 + 16) &&
                     (cx0 >= rx0) && (cx1 < rx0 + 16);
        if (inreg) {
            int ly0 = cy0 - ry0, ly1 = cy1 - ry0;
            int lx0 = cx0 - rx0, lx1 = cx1 - rx0;
            sOff[b+0] = ly0*17 + lx0;
            sOff[b+1] = ly0*17 + lx1;
            sOff[b+2] = ly1*17 + lx0;
            sOff[b+3] = ly1*17 + lx1;
            sFlag[idx] = 1;
        } else {
            sOff[b+0] = cy0*W + cx0;
            sOff[b+1] = cy0*W + cx1;
            sOff[b+2] = cy1*W + cx0;
            sOff[b+3] = cy1*W + cx1;
            sFlag[idx] = 0;
        }
    }
    __syncthreads();

    const int ocg = tid >> 4;   // 0..15 (4 oc each)
    const int pxg = tid & 15;   // 0..15 (4 px each)
    ull acc[2][4];
#pragma unroll
    for (int a = 0; a < 2; a++)
#pragma unroll
        for (int jj = 0; jj < 4; jj++) acc[a][jj] = 0ull;

    for (int ch0 = 0; ch0 < 128; ch0 += 8) {
        // channel-chunk base (chunks never straddle the 64-ch boundary)
        const float* base = (ch0 < 64)
            ? src0 + ((size_t)n*64 + ch0)*HW
            : src1 + ((size_t)n*64 + (ch0-64))*HW;

        // phase 1: stage 8ch x 16x16 halo tile (coalesced) + weight chunk
#pragma unroll
        for (int j = 0; j < 8; j++) {
            int idx = tid + j*256;          // 0..2047
            int ch = idx >> 8, rem = idx & 255;
            int r = rem >> 4, c = rem & 15;
            int gy = ry0 + r, gx = rx0 + c;
            float v = 0.f;
            if ((unsigned)gy < H && (unsigned)gx < W)
                v = __ldg(base + (size_t)ch*HW + gy*W + gx);
            sTile[ch*272 + r*17 + c] = v;
        }
        {
            const float4* ws = wT4 + (size_t)ch0*144;   // 1152 float4
#pragma unroll
            for (int j = 0; j < 5; j++) {
                int idx4 = tid + j*256;
                if (idx4 < 1152) ((float4*)sWt)[idx4] = ws[idx4];
            }
        }
        __syncthreads();

        // phase 2: gather (LDS fast path / LDG fallback), write sS[cl][pair]
        for (int pair = tid; pair < 576; pair += 256) {
            const float4 wq = *(const float4*)&sWgt[pair<<2];
            const int4   oq = *(const int4*)  &sOff[pair<<2];
            float* sdst = sS + pair;
            if (sFlag[pair]) {
                const float* ta = sTile + oq.x;
                const float* tb = sTile + oq.y;
                const float* tc = sTile + oq.z;
                const float* td = sTile + oq.w;
#pragma unroll
                for (int cl = 0; cl < 8; cl++) {
                    float v = wq.x * ta[cl*272] + wq.y * tb[cl*272]
                            + wq.z * tc[cl*272] + wq.w * td[cl*272];
                    sdst[cl*576] = v;
                }
            } else {
                const float* pa = base + oq.x;
                const float* pb = base + oq.y;
                const float* pc = base + oq.z;
                const float* pd = base + oq.w;
#pragma unroll
                for (int cl = 0; cl < 8; cl++) {
                    float v = wq.x * __ldg(pa) + wq.y * __ldg(pb)
                            + wq.z * __ldg(pc) + wq.w * __ldg(pd);
                    sdst[cl*576] = v;
                    pa += HW; pb += HW; pc += HW; pd += HW;
                }
            }
        }
        __syncthreads();

        // phase 3: GEMM
#pragma unroll 4
        for (int kk = 0; kk < 72; kk++) {
            const ull* w2 = (const ull*)&sWt[kk*64 + (ocg<<2)];
            ull w20 = w2[0], w21 = w2[1];
            const int cl = kk/9, k = kk - cl*9;
            const float4 s4 = *(const float4*)&sS[cl*576 + k*64 + (pxg<<2)];
            ull s0 = bcast2(s4.x), s1 = bcast2(s4.y);
            ull s2 = bcast2(s4.z), s3 = bcast2(s4.w);
            ffma2(acc[0][0], w20, s0); ffma2(acc[1][0], w21, s0);
            ffma2(acc[0][1], w20, s1); ffma2(acc[1][1], w21, s1);
            ffma2(acc[0][2], w20, s2); ffma2(acc[1][2], w21, s2);
            ffma2(acc[0][3], w20, s3); ffma2(acc[1][3], w21, s3);
        }
        __syncthreads();
    }

    const int p0 = pxg << 2;
    const int oy = ty0 + (p0 >> 3);
    const int ox = tx0 + (p0 & 7);
#pragma unroll
    for (int a = 0; a < 2; a++) {
        int oc0 = (ocg<<2) + 2*a;
        float b0 = bias[oc0], b1 = bias[oc0+1];
        size_t base0 = ((size_t)n*64 + oc0)*HW + (size_t)oy*W + ox;
        size_t base1 = base0 + HW;
#pragma unroll
        for (int jj = 0; jj < 4; jj++) {
            F2U u; u.u = acc[a][jj];
            float v0 = u.f.x + b0, v1 = u.f.y + b1;
            if (act == 0) {
                out[base0 + jj] = 1.f / (1.f + __expf(-v0));
                out[base1 + jj] = 1.f / (1.f + __expf(-v1));
            } else {
                const float* zbuf = args.zbuf[branch];
                const float* tbuf = args.tbuf[branch];
                float z0 = zbuf[base0 + jj], z1 = zbuf[base1 + jj];
                out[base0 + jj] = (1.f - z0) * tbuf[base0 + jj] + z0 * tanhf(v0);
                out[base1 + jj] = (1.f - z1) * tbuf[base1 + jj] + z1 * tanhf(v1);
            }
        }
    }
}

// ---------------------------------------------------------------------------
// NCF: 49-tap (r=3, dil=2) correlation softmax-attention sample.
// Interior pixels (77%) take an unguarded constant-offset fast path.
// ---------------------------------------------------------------------------
struct NcfArgs {
    const float* f1[2];
    const float* f2[2];
    float*       out[2];
};

#define NCF_OFF(k) ((((k)/7)*2 - 6)*W + ((k)%7)*2 - 6)

__global__ __launch_bounds__(256)
void ncf_kernel(NcfArgs args)
{
    const int branch = blockIdx.y;
    const float* __restrict__ f1   = args.f1[branch];
    const float* __restrict__ f2   = args.f2[branch];
    float*       __restrict__ rout = args.out[branch];

    const int tid = threadIdx.x;
    const int cg  = tid & 3;
    const int pl  = tid >> 2;
    const int gp  = blockIdx.x * 64 + pl;
    const int n   = gp / HW;
    const int pix = gp % HW;
    const int y   = pix / W, x = pix % W;
    const bool safe = (y >= 6) && (y < H-6) && (x >= 6) && (x < W-6);

    float corr[49];
#pragma unroll
    for (int k = 0; k < 49; k++) corr[k] = 0.f;

    const float* f1b = f1 + (size_t)n*64*HW + pix;
    const float* f2b = f2 + (size_t)n*64*HW + pix;

    unsigned long long vmask = 0ull;
    if (safe) {
#pragma unroll 1
        for (int ci = 0; ci < 16; ci++) {
            int c = cg*16 + ci;
            float a = f1b[(size_t)c*HW];
            const float* fp = f2b + (size_t)c*HW;
#pragma unroll
            for (int k = 0; k < 49; k++)
                corr[k] = fmaf(a, __ldg(fp + NCF_OFF(k)), corr[k]);
        }
    } else {
#pragma unroll
        for (int k = 0; k < 49; k++) {
            int yy = y + (k/7)*2 - 6;
            int xx = x + (k%7)*2 - 6;
            if ((unsigned)yy < H && (unsigned)xx < W) vmask |= (1ull << k);
        }
#pragma unroll 1
        for (int ci = 0; ci < 16; ci++) {
            int c = cg*16 + ci;
            float a = f1b[(size_t)c*HW];
            const float* fp = f2b + (size_t)c*HW;
#pragma unroll
            for (int k = 0; k < 49; k++) {
                float v = ((vmask >> k) & 1ull) ? __ldg(fp + NCF_OFF(k)) : 0.f;
                corr[k] = fmaf(a, v, corr[k]);
            }
        }
    }
#pragma unroll
    for (int k = 0; k < 49; k++) {
        corr[k] += __shfl_xor_sync(0xffffffffu, corr[k], 1);
        corr[k] += __shfl_xor_sync(0xffffffffu, corr[k], 2);
        corr[k] *= 0.125f;   // 1/sqrt(64)
    }
    float mx = corr[0];
#pragma unroll
    for (int k = 1; k < 49; k++) mx = fmaxf(mx, corr[k]);
    float s = 0.f;
#pragma unroll
    for (int k = 0; k < 49; k++) { corr[k] = __expf(corr[k] - mx); s += corr[k]; }
    float inv = 1.f / s;
#pragma unroll
    for (int k = 0; k < 49; k++) corr[k] *= inv;

    if (safe) {
#pragma unroll 1
        for (int ci = 0; ci < 16; ci++) {
            int c = cg*16 + ci;
            const float* fp = f2b + (size_t)c*HW;
            float av = 0.f;
#pragma unroll
            for (int k = 0; k < 49; k++)
                av = fmaf(corr[k], __ldg(fp + NCF_OFF(k)), av);
            rout[((size_t)n*64 + c)*HW + pix] = av;
        }
    } else {
#pragma unroll 1
        for (int ci = 0; ci < 16; ci++) {
            int c = cg*16 + ci;
            const float* fp = f2b + (size_t)c*HW;
            float av = 0.f;
#pragma unroll
            for (int k = 0; k < 49; k++) {
                float v = ((vmask >> k) & 1ull) ? __ldg(fp + NCF_OFF(k)) : 0.f;
                av = fmaf(corr[k], v, av);
            }
            rout[((size_t)n*64 + c)*HW + pix] = av;
        }
    }
}

// ---------------------------------------------------------------------------
extern "C" void kernel_launch(void* const* d_in, const int* in_sizes, int n_in,
                              void* d_out, int out_size)
{
    const float* X    = (const float*)d_in[0];
    const float* T    = (const float*)d_in[1];
    const float* Wi   = (const float*)d_in[2];
    const float* Bi   = (const float*)d_in[3];
    const float* Wo   = (const float*)d_in[4];
    const float* Bo   = (const float*)d_in[5];
    const float* EZW  = (const float*)d_in[6];
    const float* EZB  = (const float*)d_in[7];
    const float* EZOW = (const float*)d_in[8];
    const float* EZOB = (const float*)d_in[9];
    const float* EHW  = (const float*)d_in[10];
    const float* EHB  = (const float*)d_in[11];
    const float* EHOW = (const float*)d_in[12];
    const float* EHOB = (const float*)d_in[13];
    const float* UZW  = (const float*)d_in[14];
    const float* UZB  = (const float*)d_in[15];
    const float* UZOW = (const float*)d_in[16];
    const float* UZOB = (const float*)d_in[17];
    const float* UHW  = (const float*)d_in[18];
    const float* UHB  = (const float*)d_in[19];
    const float* UHOW = (const float*)d_in[20];
    const float* UHOB = (const float*)d_in[21];

    float* out  = (float*)d_out;
    float* newt = out + (size_t)NB*CIN*HW;

    float *xh, *om0, *om1, *z0, *z1, *r0, *r1, *xe;
    float *cwi, *cwo, *owt, *dwt;
    cudaGetSymbolAddress((void**)&xh,  g_xh);
    cudaGetSymbolAddress((void**)&om0, g_om0);
    cudaGetSymbolAddress((void**)&om1, g_om1);
    cudaGetSymbolAddress((void**)&z0,  g_z0);
    cudaGetSymbolAddress((void**)&z1,  g_z1);
    cudaGetSymbolAddress((void**)&r0,  g_r0);
    cudaGetSymbolAddress((void**)&r1,  g_r1);
    cudaGetSymbolAddress((void**)&xe,  g_xe);
    cudaGetSymbolAddress((void**)&cwi, g_cwT_in);
    cudaGetSymbolAddress((void**)&cwo, g_cwT_out);
    cudaGetSymbolAddress((void**)&owt, g_owT);
    cudaGetSymbolAddress((void**)&dwt, g_dwT);

    float* owT0 = owt;               // EZ offset
    float* owT1 = owt + 1*36864;     // UZ offset
    float* owT2 = owt + 2*36864;     // EH offset
    float* owT3 = owt + 3*36864;     // UH offset
    float* dwT0 = dwt;               // EZ dcn
    float* dwT1 = dwt + 1*73728;     // EH dcn
    float* dwT2 = dwt + 2*73728;     // UZ dcn
    float* dwT3 = dwt + 3*73728;     // UH dcn

    cudaFuncSetAttribute(dcn_kernel,
                         cudaFuncAttributeMaxDynamicSharedMemorySize, DCN_SMEM);

    // L0: weight transposition (tiny)
    {
        PrepJobs pj;
        const float* srcs[10] = {Wi, Wo, EZOW, UZOW, EHOW, UHOW, EZW, EHW, UZW, UHW};
        float* dsts[10] = {cwi, cwo, owT0, owT1, owT2, owT3, dwT0, dwT1, dwT2, dwT3};
        int cins [10] = {256, 64, 128, 128, 128, 128, 128, 128, 128, 128};
        int couts[10] = {64, 256, 27, 27, 27, 27, 64, 64, 64, 64};
        int pads [10] = {64, 256, 32, 32, 32, 32, 64, 64, 64, 64};
        for (int i = 0; i < 10; i++) {
            pj.src[i] = srcs[i]; pj.dst[i] = dsts[i];
            pj.cin[i] = cins[i]; pj.cout[i] = couts[i]; pj.pad[i] = pads[i];
            pj.total[i] = cins[i]*9*pads[i];
        }
        prep_kernel<<<dim3(576, 10), 256>>>(pj);
    }

    // L1: xh = conv_in(x)  (OCT=64, Cout=64)
    {
        ConvArgs a = { {X,X},{X,X},{cwi,cwi},{Bi,Bi},{xh,xh} };
        conv3x3_kernel<64><<<dim3(144, 1, NB), 256>>>(a, CIN, CIN, CH, 64);
    }
    // L2: offset conv z, both branches (OCT=32, Cout=27)
    {
        ConvArgs a = { {T,xh},{xh,T},{owT0,owT1},{EZOB,UZOB},{om0,om1} };
        conv3x3_kernel<32><<<dim3(144, 1, 2*NB), 256>>>(a, CH, 2*CH, 27, 32);
    }
    // L3: dcn z, both branches (sigmoid)
    {
        DcnArgs a = { {T,xh},{xh,T},{om0,om1},{dwT0,dwT2},{EZB,UZB},
                      {z0,z1},{nullptr,nullptr},{nullptr,nullptr} };
        dcn_kernel<<<dim3(144, 2, NB), 256, DCN_SMEM>>>(a, 0);
    }
    // L4: ncf, both branches
    {
        NcfArgs a = { {xh,T},{T,xh},{r0,r1} };
        ncf_kernel<<<dim3(NB*HW/64, 2), 256>>>(a);
    }
    // L5: offset conv h, both branches
    {
        ConvArgs a = { {r0,r1},{xh,T},{owT2,owT3},{EHOB,UHOB},{om0,om1} };
        conv3x3_kernel<32><<<dim3(144, 1, 2*NB), 256>>>(a, CH, 2*CH, 27, 32);
    }
    // L6: dcn h + fused GRU combine, both branches
    {
        DcnArgs a = { {r0,r1},{xh,T},{om0,om1},{dwT1,dwT3},{EHB,UHB},
                      {xe,newt},{z0,z1},{xh,T} };
        dcn_kernel<<<dim3(144, 2, NB), 256, DCN_SMEM>>>(a, 1);
    }
    // L7: out = conv_out(x_enh)  (OCT=64, Cout=256)
    {
        ConvArgs a = { {xe,xe},{xe,xe},{cwo,cwo},{Bo,Bo},{out,out} };
        conv3x3_kernel<64><<<dim3(144, 4, NB), 256>>>(a, CH, CH, CIN, 256);
    }
}